// round 14
// baseline (speedup 1.0000x reference)
#include <cuda_runtime.h>

// ---------------- problem constants ----------------
#define NSEQ  704          // B*F
#define TT    512
#define HDIM  64
#define GDIM  192          // 3*H
#define MROWS (NSEQ*TT)    // 360448
// recur partition: per dir, 38 CTAs x 4 seqs + 184 CTAs x 3 seqs = 704
#define RCPD   222         // recur CTAs per dir
#define NHEAVY 38          // heavy (4-seq) CTAs per dir
#define RMAX   4

// ---------------- scratch (device globals; no allocation) ----------------
__device__ float g_pre[(size_t)2 * MROWS * GDIM];   // [dir][row][192]
__device__ float g_hbuf[(size_t)MROWS * 128];       // [row][2*H]

typedef unsigned long long u64;

__device__ __forceinline__ u64 fma2(u64 a, u64 b, u64 c) {
    u64 d;
    asm("fma.rn.f32x2 %0, %1, %2, %3;" : "=l"(d) : "l"(a), "l"(b), "l"(c));
    return d;
}
__device__ __forceinline__ float2 u2f(u64 v) {
    float2 r;
    asm("mov.b64 {%0,%1}, %2;" : "=f"(r.x), "=f"(r.y) : "l"(v));
    return r;
}
__device__ __forceinline__ float tanh_fast(float x) {
    float y;
    asm("tanh.approx.f32 %0, %1;" : "=f"(y) : "f"(x));
    return y;
}
__device__ __forceinline__ float sig_fast(float x) {
    return 0.5f * tanh_fast(0.5f * x) + 0.5f;
}
__device__ __forceinline__ float sig_acc(float x) {
    return __fdividef(1.f, 1.f + __expf(-x));
}

// ---------------- layer-0 projection (KD=64): 2 gate rows per thread ----------------
__global__ __launch_bounds__(192, 2)
void proj0_kernel(const float* __restrict__ xin,
                  const float* __restrict__ W,     // [384][64]
                  const float* __restrict__ bias)  // [384]
{
    const int tid  = threadIdx.x;
    const int row0 = blockIdx.x * 256;

    __shared__ __align__(16) float xs[2][32 * 64];

    const int j0 = 2 * tid;
    const int d  = (j0 >= GDIM) ? 1 : 0;
    const int g0 = j0 - d * GDIM;

    u64 w[2][32];
    const u64* wr = (const u64*)(W + (size_t)j0 * 64);
#pragma unroll
    for (int q = 0; q < 32; q++) { w[0][q] = wr[q]; w[1][q] = wr[32 + q]; }
    const float2 b2 = *(const float2*)(bias + j0);

    float* op = g_pre + ((size_t)d * MROWS + row0) * GDIM + g0;

    {   // chunk 0 (contiguous copy)
        const float4* s4 = (const float4*)(xin + (size_t)row0 * 64);
        for (int i = tid; i < 512; i += 192) ((float4*)xs[0])[i] = s4[i];
    }
    __syncthreads();

#pragma unroll 1
    for (int c = 0; c < 8; c++) {
        const int buf = c & 1;
        if (c < 7) {
            const float4* s4 = (const float4*)(xin + (size_t)(row0 + (c + 1) * 32) * 64);
            for (int i = tid; i < 512; i += 192) ((float4*)xs[buf ^ 1])[i] = s4[i];
        }
#pragma unroll 1
        for (int r = 0; r < 32; r++) {
            const ulonglong2* xp = (const ulonglong2*)(xs[buf] + r * 64);
            u64 a0 = 0, a1 = 0, a2 = 0, a3 = 0;
#pragma unroll
            for (int q = 0; q < 16; q++) {
                ulonglong2 v = xp[q];
                a0 = fma2(w[0][2 * q + 0], v.x, a0);
                a1 = fma2(w[0][2 * q + 1], v.y, a1);
                a2 = fma2(w[1][2 * q + 0], v.x, a2);
                a3 = fma2(w[1][2 * q + 1], v.y, a3);
            }
            float2 f0 = u2f(a0), f1 = u2f(a1), f2_ = u2f(a2), f3 = u2f(a3);
            float s0 = (f0.x + f0.y) + (f1.x + f1.y) + b2.x;
            float s1 = (f2_.x + f2_.y) + (f3.x + f3.y) + b2.y;
            *(float2*)(op + (size_t)(c * 32 + r) * GDIM) = make_float2(s0, s1);
        }
        __syncthreads();
    }
}

// ---------------- layer-1 projection (KD=128): split-K, 2 rows per thread-pair ----------------
__global__ __launch_bounds__(384)
void proj1_kernel(const float* __restrict__ W,     // [384][128]
                  const float* __restrict__ bias)  // [384]
{
    const float* in = (const float*)g_hbuf;
    const int tid  = threadIdx.x;
    const int row0 = blockIdx.x * 256;

    __shared__ __align__(16) float xs[2][32 * 132];   // 132 = 64 + 4 pad + 64

    const int m  = tid >> 1;
    const int kh = tid & 1;
    const int j0 = 2 * m;
    const int d  = (j0 >= GDIM) ? 1 : 0;
    const int g0 = j0 - d * GDIM;

    u64 w[2][32];
    const u64* wr = (const u64*)(W + (size_t)j0 * 128);
#pragma unroll
    for (int q = 0; q < 32; q++) {
        w[0][q] = wr[kh * 32 + q];
        w[1][q] = wr[64 + kh * 32 + q];
    }
    const float2 b2 = *(const float2*)(bias + j0);

    float* op = g_pre + ((size_t)d * MROWS + row0) * GDIM + g0;

    auto load_chunk = [&](int c, int buf) {
        const float4* s4 = (const float4*)(in + (size_t)(row0 + c * 32) * 128);
        for (int i = tid; i < 1024; i += 384) {
            int r = i >> 5, jj = i & 31;
            int dstf = r * 132 + ((jj < 16) ? jj * 4 : 68 + (jj - 16) * 4);
            *(float4*)(xs[buf] + dstf) = s4[i];
        }
    };

    load_chunk(0, 0);
    __syncthreads();

#pragma unroll 1
    for (int c = 0; c < 8; c++) {
        const int buf = c & 1;
        if (c < 7) load_chunk(c + 1, buf ^ 1);
#pragma unroll 1
        for (int r = 0; r < 32; r++) {
            const ulonglong2* xp = (const ulonglong2*)(xs[buf] + r * 132 + kh * 68);
            u64 a0 = 0, a1 = 0, a2 = 0, a3 = 0;
#pragma unroll
            for (int q = 0; q < 16; q++) {
                ulonglong2 v = xp[q];
                a0 = fma2(w[0][2 * q + 0], v.x, a0);
                a1 = fma2(w[0][2 * q + 1], v.y, a1);
                a2 = fma2(w[1][2 * q + 0], v.x, a2);
                a3 = fma2(w[1][2 * q + 1], v.y, a3);
            }
            float2 f0 = u2f(a0), f1 = u2f(a1), f2_ = u2f(a2), f3 = u2f(a3);
            float s0 = (f0.x + f0.y) + (f1.x + f1.y);
            float s1 = (f2_.x + f2_.y) + (f3.x + f3.y);
            s0 += __shfl_xor_sync(0xffffffffu, s0, 1);
            s1 += __shfl_xor_sync(0xffffffffu, s1, 1);
            if (kh == 0)
                *(float2*)(op + (size_t)(c * 32 + r) * GDIM) =
                    make_float2(s0 + b2.x, s1 + b2.y);
        }
        __syncthreads();
    }
}

// ---------------- recurrence v3: balanced exact partition, 96 threads, 2 gates/thread ----------
// 444 CTAs total (222 per dir), 3 per SM exactly. Heavy CTAs (4 seqs) are bids
// 0-37 and 222-259 -> disjoint SMs under bid%148 placement; max SM load = 10
// seq-dirs vs avg 9.5 (was 12 vs 9.5). ns is CTA-uniform; seq loops use
// compile-time indices with uniform `q < ns` guards (no local-memory arrays).
__global__ __launch_bounds__(96, 3)
void recur_kernel(const float* __restrict__ Whh,   // [2][192][64]
                  const float* __restrict__ bhh)   // [2][192]
{
    const int c    = blockIdx.x;
    const int d    = c / RCPD;
    const int cl   = c - d * RCPD;
    const bool hv  = (cl < NHEAVY);
    const int ns   = hv ? 4 : 3;
    const int n0   = hv ? cl * 4 : (NHEAVY * 4 + (cl - NHEAVY) * 3);
    const int tid  = threadIdx.x;
    const int g0   = 2 * tid;

    __shared__ float h_sh[RMAX][64];
    __shared__ float s_v[RMAX][256];

    u64 w[2][32];
    const u64* wr = (const u64*)(Whh + ((size_t)d * GDIM + g0) * HDIM);
#pragma unroll
    for (int q = 0; q < 32; q++) { w[0][q] = wr[q]; w[1][q] = wr[32 + q]; }
    const float2 bh = *(const float2*)(bhh + d * GDIM + g0);

    for (int i = tid; i < RMAX * 64; i += 96) ((float*)h_sh)[i] = 0.f;
    __syncthreads();

    const int t0  = d ? (TT - 1) : 0;
    const int dt  = d ? -1 : 1;
    const long dtG = (long)dt * GDIM;
    const long dtH = (long)dt * 128;

    // per-seq pre pointers (exact partition: all ns seqs valid)
    const float* pcur[RMAX];
#pragma unroll
    for (int q = 0; q < RMAX; q++) {
        int nq = (q < ns) ? (n0 + q) : n0;
        pcur[q] = g_pre + ((size_t)d * MROWS + (size_t)nq * TT + t0) * GDIM + g0;
    }

    // activation slots: slot = tid + k*96, k = 0..2; valid if slot < ns*64
    int  sA[3], iA[3];
    bool vA[3];
    float* hp[3];
#pragma unroll
    for (int k = 0; k < 3; k++) {
        int slot = tid + k * 96;
        vA[k] = (slot < ns * 64);
        sA[k] = slot >> 6;
        iA[k] = slot & 63;
        int nq = vA[k] ? (n0 + sA[k]) : n0;
        hp[k]  = g_hbuf + ((size_t)nq * TT + t0) * 128 + d * 64 + iA[k];
    }

    float2 pc[RMAX];
#pragma unroll
    for (int q = 0; q < RMAX; q++) {
        if (q < ns) { pc[q] = __ldg((const float2*)pcur[q]); pcur[q] += dtG; }
    }

#pragma unroll 1
    for (int step = 0; step < TT; step++) {
        float2 pn[RMAX];
        if (step < TT - 1) {
#pragma unroll
            for (int q = 0; q < RMAX; q++) {
                if (q < ns) { pn[q] = __ldg((const float2*)pcur[q]); pcur[q] += dtG; }
            }
        }

        // phase A: hh dot products, 2 gates x ns seqs
#pragma unroll
        for (int seq = 0; seq < RMAX; seq++) {
            if (seq < ns) {
                const ulonglong2* h2 = (const ulonglong2*)h_sh[seq];
                u64 a0 = 0, a1 = 0, a2 = 0, a3 = 0;
#pragma unroll
                for (int q = 0; q < 16; q++) {
                    ulonglong2 v = h2[q];
                    a0 = fma2(w[0][2 * q + 0], v.x, a0);
                    a1 = fma2(w[0][2 * q + 1], v.y, a1);
                    a2 = fma2(w[1][2 * q + 0], v.x, a2);
                    a3 = fma2(w[1][2 * q + 1], v.y, a3);
                }
                float2 f0 = u2f(a0), f1 = u2f(a1), f2_ = u2f(a2), f3 = u2f(a3);
                float hh0 = (f0.x + f0.y) + (f1.x + f1.y) + bh.x;
                float hh1 = (f2_.x + f2_.y) + (f3.x + f3.y) + bh.y;
                float2 pcv = pc[seq];
                if (g0 < 128) {      // both gates are r or z: store pre+hh
                    *(float2*)&s_v[seq][g0] = make_float2(hh0 + pcv.x, hh1 + pcv.y);
                } else {             // both gates are n: keep hh and pre separate
                    *(float2*)&s_v[seq][g0]      = make_float2(hh0, hh1);
                    *(float2*)&s_v[seq][g0 + 64] = pcv;
                }
            }
        }
        __syncthreads();

        // phase B: activations, ns*64 slots over 96 threads (<=3 each)
#pragma unroll
        for (int k = 0; k < 3; k++) {
            if (vA[k]) {
                const float* sv = s_v[sA[k]];
                int idx = iA[k];
                float r    = sig_fast(sv[idx]);
                float z    = sig_fast(sv[64 + idx]);
                float nn   = tanh_fast(sv[192 + idx] + r * sv[128 + idx]);
                float hold = h_sh[sA[k]][idx];
                float hnew = nn + z * (hold - nn);
                h_sh[sA[k]][idx] = hnew;
                *hp[k] = hnew;
            }
            hp[k] += dtH;
        }
        __syncthreads();

#pragma unroll
        for (int q = 0; q < RMAX; q++) pc[q] = pn[q];
    }
}

// ---------------- FC head: 2 outputs per warp (MLP=2) ----------------
__global__ void fc_kernel(const float* __restrict__ fcw,
                          const float* __restrict__ fcb,
                          float* __restrict__ out)
{
    int wid  = threadIdx.x >> 5;
    int lane = threadIdx.x & 31;
    size_t g0 = (size_t)blockIdx.x * 16 + wid * 2;

    float4 w4 = *(const float4*)(fcw + lane * 4);
    float4 v0 = *(const float4*)(g_hbuf + g0 * 128 + lane * 4);
    float4 v1 = *(const float4*)(g_hbuf + (g0 + 1) * 128 + lane * 4);
    float d0 = v0.x * w4.x + v0.y * w4.y + v0.z * w4.z + v0.w * w4.w;
    float d1 = v1.x * w4.x + v1.y * w4.y + v1.z * w4.z + v1.w * w4.w;
#pragma unroll
    for (int o = 16; o > 0; o >>= 1) {
        d0 += __shfl_down_sync(0xffffffffu, d0, o);
        d1 += __shfl_down_sync(0xffffffffu, d1, o);
    }
    if (lane == 0) {
        float bb = fcb[0];
#pragma unroll
        for (int k = 0; k < 2; k++) {
            size_t g = g0 + k;
            float dv = k ? d1 : d0;
            int nidx = (int)(g / TT), t = (int)(g % TT);
            int b = nidx / 88, f = nidx % 88;
            out[((size_t)b * TT + t) * 88 + f] = sig_acc(dv + bb);
        }
    }
}

// ---------------- launch ----------------
extern "C" void kernel_launch(void* const* d_in, const int* in_sizes, int n_in,
                              void* d_out, int out_size)
{
    const float* x    = (const float*)d_in[0];
    const float* Wih0 = (const float*)d_in[1];
    const float* Whh0 = (const float*)d_in[2];
    const float* bih0 = (const float*)d_in[3];
    const float* bhh0 = (const float*)d_in[4];
    const float* Wih1 = (const float*)d_in[5];
    const float* Whh1 = (const float*)d_in[6];
    const float* bih1 = (const float*)d_in[7];
    const float* bhh1 = (const float*)d_in[8];
    const float* fcw  = (const float*)d_in[9];
    const float* fcb  = (const float*)d_in[10];
    float* out = (float*)d_out;

    proj0_kernel<<<MROWS / 256, 192>>>(x, Wih0, bih0);      // L0 input proj
    recur_kernel<<<2 * RCPD, 96>>>(Whh0, bhh0);             // L0 GRU (balanced)
    proj1_kernel<<<MROWS / 256, 384>>>(Wih1, bih1);         // L1 input proj (reads g_hbuf)
    recur_kernel<<<2 * RCPD, 96>>>(Whh1, bhh1);             // L1 GRU (balanced)
    fc_kernel<<<MROWS / 16, 256>>>(fcw, fcb, out);          // FC + sigmoid
}

// round 15
// speedup vs baseline: 1.1511x; 1.1511x over previous
#include <cuda_runtime.h>

// ---------------- problem constants ----------------
#define NSEQ  704          // B*F
#define TT    512
#define HDIM  64
#define GDIM  192          // 3*H
#define MROWS (NSEQ*TT)    // 360448
#define RSPC  3            // sequences per recur CTA (per dir)
#define NCTA_R ((NSEQ + RSPC - 1) / RSPC)   // 235

// ---------------- scratch (device globals; no allocation) ----------------
__device__ float g_pre[(size_t)2 * MROWS * GDIM];   // [dir][row][192]
__device__ float g_hbuf[(size_t)MROWS * 128];       // [row][2*H]

typedef unsigned long long u64;

__device__ __forceinline__ u64 fma2(u64 a, u64 b, u64 c) {
    u64 d;
    asm("fma.rn.f32x2 %0, %1, %2, %3;" : "=l"(d) : "l"(a), "l"(b), "l"(c));
    return d;
}
__device__ __forceinline__ float2 u2f(u64 v) {
    float2 r;
    asm("mov.b64 {%0,%1}, %2;" : "=f"(r.x), "=f"(r.y) : "l"(v));
    return r;
}
__device__ __forceinline__ float tanh_fast(float x) {
    float y;
    asm("tanh.approx.f32 %0, %1;" : "=f"(y) : "f"(x));
    return y;
}
__device__ __forceinline__ float sig_fast(float x) {
    return 0.5f * tanh_fast(0.5f * x) + 0.5f;
}
__device__ __forceinline__ float sig_acc(float x) {
    return __fdividef(1.f, 1.f + __expf(-x));
}

// ---------------- layer-0 projection (KD=64): 2 gate rows per thread ----------------
__global__ __launch_bounds__(192, 2)
void proj0_kernel(const float* __restrict__ xin,
                  const float* __restrict__ W,     // [384][64]
                  const float* __restrict__ bias)  // [384]
{
    const int tid  = threadIdx.x;
    const int row0 = blockIdx.x * 256;

    __shared__ __align__(16) float xs[2][32 * 64];

    const int j0 = 2 * tid;
    const int d  = (j0 >= GDIM) ? 1 : 0;
    const int g0 = j0 - d * GDIM;

    u64 w[2][32];
    const u64* wr = (const u64*)(W + (size_t)j0 * 64);
#pragma unroll
    for (int q = 0; q < 32; q++) { w[0][q] = wr[q]; w[1][q] = wr[32 + q]; }
    const float2 b2 = *(const float2*)(bias + j0);

    float* op = g_pre + ((size_t)d * MROWS + row0) * GDIM + g0;

    {   // chunk 0 (contiguous copy)
        const float4* s4 = (const float4*)(xin + (size_t)row0 * 64);
        for (int i = tid; i < 512; i += 192) ((float4*)xs[0])[i] = s4[i];
    }
    __syncthreads();

#pragma unroll 1
    for (int c = 0; c < 8; c++) {
        const int buf = c & 1;
        if (c < 7) {
            const float4* s4 = (const float4*)(xin + (size_t)(row0 + (c + 1) * 32) * 64);
            for (int i = tid; i < 512; i += 192) ((float4*)xs[buf ^ 1])[i] = s4[i];
        }
#pragma unroll 1
        for (int r = 0; r < 32; r++) {
            const ulonglong2* xp = (const ulonglong2*)(xs[buf] + r * 64);
            u64 a0 = 0, a1 = 0, a2 = 0, a3 = 0;
#pragma unroll
            for (int q = 0; q < 16; q++) {
                ulonglong2 v = xp[q];
                a0 = fma2(w[0][2 * q + 0], v.x, a0);
                a1 = fma2(w[0][2 * q + 1], v.y, a1);
                a2 = fma2(w[1][2 * q + 0], v.x, a2);
                a3 = fma2(w[1][2 * q + 1], v.y, a3);
            }
            float2 f0 = u2f(a0), f1 = u2f(a1), f2_ = u2f(a2), f3 = u2f(a3);
            float s0 = (f0.x + f0.y) + (f1.x + f1.y) + b2.x;
            float s1 = (f2_.x + f2_.y) + (f3.x + f3.y) + b2.y;
            *(float2*)(op + (size_t)(c * 32 + r) * GDIM) = make_float2(s0, s1);
        }
        __syncthreads();
    }
}

// ---------------- layer-1 projection (KD=128): split-K pairs, ONE dir per CTA ----------------
// 192 threads, occ 2 (vs previous 384-thread occ-1 version): a second CTA per SM
// hides the chunk-load/sync phases. m=tid/2 picks rows 2m,2m+1 of dir blockIdx.y;
// kh=tid&1 picks K-half (32 u64 regs/row). Partner halves combined via shfl_xor(1).
__global__ __launch_bounds__(192, 2)
void proj1_kernel(const float* __restrict__ W,     // [2][192][128]
                  const float* __restrict__ bias)  // [2][192]
{
    const float* in = (const float*)g_hbuf;
    const int tid  = threadIdx.x;
    const int row0 = blockIdx.x * 256;
    const int d    = blockIdx.y;

    __shared__ __align__(16) float xs[2][32 * 132];   // 132 = 64 + 4 pad + 64

    const int m  = tid >> 1;          // 0..95 -> rows 2m, 2m+1 of this dir
    const int kh = tid & 1;
    const int g0 = 2 * m;

    u64 w[2][32];
    const u64* wr = (const u64*)(W + ((size_t)d * GDIM + g0) * 128);
#pragma unroll
    for (int q = 0; q < 32; q++) {
        w[0][q] = wr[kh * 32 + q];
        w[1][q] = wr[64 + kh * 32 + q];
    }
    const float2 b2 = *(const float2*)(bias + d * GDIM + g0);

    float* op = g_pre + ((size_t)d * MROWS + row0) * GDIM + g0;

    auto load_chunk = [&](int c, int buf) {
        const float4* s4 = (const float4*)(in + (size_t)(row0 + c * 32) * 128);
        for (int i = tid; i < 1024; i += 192) {
            int r = i >> 5, jj = i & 31;
            int dstf = r * 132 + ((jj < 16) ? jj * 4 : 68 + (jj - 16) * 4);
            *(float4*)(xs[buf] + dstf) = s4[i];
        }
    };

    load_chunk(0, 0);
    __syncthreads();

#pragma unroll 1
    for (int c = 0; c < 8; c++) {
        const int buf = c & 1;
        if (c < 7) load_chunk(c + 1, buf ^ 1);
#pragma unroll 1
        for (int r = 0; r < 32; r++) {
            const ulonglong2* xp = (const ulonglong2*)(xs[buf] + r * 132 + kh * 68);
            u64 a0 = 0, a1 = 0, a2 = 0, a3 = 0;
#pragma unroll
            for (int q = 0; q < 16; q++) {
                ulonglong2 v = xp[q];
                a0 = fma2(w[0][2 * q + 0], v.x, a0);
                a1 = fma2(w[0][2 * q + 1], v.y, a1);
                a2 = fma2(w[1][2 * q + 0], v.x, a2);
                a3 = fma2(w[1][2 * q + 1], v.y, a3);
            }
            float2 f0 = u2f(a0), f1 = u2f(a1), f2_ = u2f(a2), f3 = u2f(a3);
            float s0 = (f0.x + f0.y) + (f1.x + f1.y);
            float s1 = (f2_.x + f2_.y) + (f3.x + f3.y);
            s0 += __shfl_xor_sync(0xffffffffu, s0, 1);
            s1 += __shfl_xor_sync(0xffffffffu, s1, 1);
            if (kh == 0)
                *(float2*)(op + (size_t)(c * 32 + r) * GDIM) =
                    make_float2(s0 + b2.x, s1 + b2.y);
        }
        __syncthreads();
    }
}

// ---------------- recurrence: R12-proven (96 threads, 2 gates/thread, SPC=3, occ 4) ----------
__global__ __launch_bounds__(96, 4)
void recur_kernel(const float* __restrict__ Whh,   // [2][192][64]
                  const float* __restrict__ bhh)   // [2][192]
{
    const int d   = blockIdx.y;
    const int n0  = blockIdx.x * RSPC;
    const int tid = threadIdx.x;
    const int g0  = 2 * tid;

    __shared__ float h_sh[RSPC][64];
    __shared__ float s_v[RSPC][256];

    u64 w[2][32];
    const u64* wr = (const u64*)(Whh + ((size_t)d * GDIM + g0) * HDIM);
#pragma unroll
    for (int q = 0; q < 32; q++) { w[0][q] = wr[q]; w[1][q] = wr[32 + q]; }
    const float2 bh = *(const float2*)(bhh + d * GDIM + g0);

    ((float*)h_sh)[tid] = 0.f;
    ((float*)h_sh)[tid + 96] = 0.f;
    __syncthreads();

    const int t0  = d ? (TT - 1) : 0;
    const int dt  = d ? -1 : 1;
    const long dtG = (long)dt * GDIM;
    const long dtH = (long)dt * 128;

    // per-seq pre pointers (tail CTA clamps reads to last valid seq)
    const float* pcur[RSPC];
    bool vst[RSPC];
#pragma unroll
    for (int q = 0; q < RSPC; q++) {
        int n = n0 + q;
        vst[q] = (n < NSEQ);
        int nc = vst[q] ? n : (NSEQ - 1);
        pcur[q] = g_pre + ((size_t)d * MROWS + (size_t)nc * TT + t0) * GDIM + g0;
    }

    // activation slots: tid and tid+96 over 192 slots (seq = slot/64, idx = slot%64)
    const int sA0 = tid / 64;            // 0..1
    const int iA0 = tid % 64;
    const int sA1 = (tid + 96) / 64;     // 1..2
    const int iA1 = (tid + 96) % 64;
    const bool vA0 = vst[sA0];
    const bool vA1 = vst[sA1];
    float* hp0 = g_hbuf + ((size_t)(n0 + sA0) * TT + t0) * 128 + d * 64 + iA0;
    float* hp1 = g_hbuf + ((size_t)(n0 + (vA1 ? sA1 : 0)) * TT + t0) * 128 + d * 64 + iA1;

    float2 pc[RSPC];
#pragma unroll
    for (int q = 0; q < RSPC; q++) {
        pc[q] = __ldg((const float2*)pcur[q]);
        pcur[q] += dtG;
    }

#pragma unroll 1
    for (int step = 0; step < TT; step++) {
        float2 pn[RSPC];
        if (step < TT - 1) {
#pragma unroll
            for (int q = 0; q < RSPC; q++) {
                pn[q] = __ldg((const float2*)pcur[q]);
                pcur[q] += dtG;
            }
        }

        // phase A: hh dot products, 2 gates x 3 seqs
#pragma unroll
        for (int seq = 0; seq < RSPC; seq++) {
            const ulonglong2* h2 = (const ulonglong2*)h_sh[seq];
            u64 a0 = 0, a1 = 0, a2 = 0, a3 = 0;
#pragma unroll
            for (int q = 0; q < 16; q++) {
                ulonglong2 v = h2[q];
                a0 = fma2(w[0][2 * q + 0], v.x, a0);
                a1 = fma2(w[0][2 * q + 1], v.y, a1);
                a2 = fma2(w[1][2 * q + 0], v.x, a2);
                a3 = fma2(w[1][2 * q + 1], v.y, a3);
            }
            float2 f0 = u2f(a0), f1 = u2f(a1), f2_ = u2f(a2), f3 = u2f(a3);
            float hh0 = (f0.x + f0.y) + (f1.x + f1.y) + bh.x;
            float hh1 = (f2_.x + f2_.y) + (f3.x + f3.y) + bh.y;
            float2 pcv = pc[seq];
            if (g0 < 128) {      // both gates are r or z: store pre+hh
                *(float2*)&s_v[seq][g0] = make_float2(hh0 + pcv.x, hh1 + pcv.y);
            } else {             // both gates are n: keep hh and pre separate
                *(float2*)&s_v[seq][g0]      = make_float2(hh0, hh1);
                *(float2*)&s_v[seq][g0 + 64] = pcv;
            }
        }
        __syncthreads();

        // phase B: activations, 192 slots over 96 threads (2 each)
        {
            const float* sv = s_v[sA0];
            float r    = sig_fast(sv[iA0]);
            float z    = sig_fast(sv[64 + iA0]);
            float nn   = tanh_fast(sv[192 + iA0] + r * sv[128 + iA0]);
            float hold = h_sh[sA0][iA0];
            float hnew = nn + z * (hold - nn);
            h_sh[sA0][iA0] = hnew;
            if (vA0) *hp0 = hnew;
            hp0 += dtH;
        }
        {
            const float* sv = s_v[sA1];
            float r    = sig_fast(sv[iA1]);
            float z    = sig_fast(sv[64 + iA1]);
            float nn   = tanh_fast(sv[192 + iA1] + r * sv[128 + iA1]);
            float hold = h_sh[sA1][iA1];
            float hnew = nn + z * (hold - nn);
            h_sh[sA1][iA1] = hnew;
            if (vA1) *hp1 = hnew;
            hp1 += dtH;
        }
        __syncthreads();

#pragma unroll
        for (int q = 0; q < RSPC; q++) pc[q] = pn[q];
    }
}

// ---------------- FC head: 2 outputs per warp (MLP=2) ----------------
__global__ void fc_kernel(const float* __restrict__ fcw,
                          const float* __restrict__ fcb,
                          float* __restrict__ out)
{
    int wid  = threadIdx.x >> 5;
    int lane = threadIdx.x & 31;
    size_t g0 = (size_t)blockIdx.x * 16 + wid * 2;

    float4 w4 = *(const float4*)(fcw + lane * 4);
    float4 v0 = *(const float4*)(g_hbuf + g0 * 128 + lane * 4);
    float4 v1 = *(const float4*)(g_hbuf + (g0 + 1) * 128 + lane * 4);
    float d0 = v0.x * w4.x + v0.y * w4.y + v0.z * w4.z + v0.w * w4.w;
    float d1 = v1.x * w4.x + v1.y * w4.y + v1.z * w4.z + v1.w * w4.w;
#pragma unroll
    for (int o = 16; o > 0; o >>= 1) {
        d0 += __shfl_down_sync(0xffffffffu, d0, o);
        d1 += __shfl_down_sync(0xffffffffu, d1, o);
    }
    if (lane == 0) {
        float bb = fcb[0];
#pragma unroll
        for (int k = 0; k < 2; k++) {
            size_t g = g0 + k;
            float dv = k ? d1 : d0;
            int nidx = (int)(g / TT), t = (int)(g % TT);
            int b = nidx / 88, f = nidx % 88;
            out[((size_t)b * TT + t) * 88 + f] = sig_acc(dv + bb);
        }
    }
}

// ---------------- launch ----------------
extern "C" void kernel_launch(void* const* d_in, const int* in_sizes, int n_in,
                              void* d_out, int out_size)
{
    const float* x    = (const float*)d_in[0];
    const float* Wih0 = (const float*)d_in[1];
    const float* Whh0 = (const float*)d_in[2];
    const float* bih0 = (const float*)d_in[3];
    const float* bhh0 = (const float*)d_in[4];
    const float* Wih1 = (const float*)d_in[5];
    const float* Whh1 = (const float*)d_in[6];
    const float* bih1 = (const float*)d_in[7];
    const float* bhh1 = (const float*)d_in[8];
    const float* fcw  = (const float*)d_in[9];
    const float* fcb  = (const float*)d_in[10];
    float* out = (float*)d_out;

    dim3 rg(NCTA_R, 2);
    dim3 p1g(MROWS / 256, 2);

    proj0_kernel<<<MROWS / 256, 192>>>(x, Wih0, bih0);      // L0 input proj
    recur_kernel<<<rg, 96>>>(Whh0, bhh0);                   // L0 GRU
    proj1_kernel<<<p1g, 192>>>(Wih1, bih1);                 // L1 input proj (reads g_hbuf)
    recur_kernel<<<rg, 96>>>(Whh1, bhh1);                   // L1 GRU
    fc_kernel<<<MROWS / 16, 256>>>(fcw, fcb, out);          // FC + sigmoid
}

// round 16
// speedup vs baseline: 1.2310x; 1.0694x over previous
#include <cuda_runtime.h>

// ---------------- problem constants ----------------
#define NSEQ  704          // B*F
#define TT    512
#define HDIM  64
#define GDIM  192          // 3*H
#define MROWS (NSEQ*TT)    // 360448
#define RSPC  3            // sequences per recur CTA (per dir)
#define NCTA_R ((NSEQ + RSPC - 1) / RSPC)   // 235

// ---------------- scratch (device globals; no allocation) ----------------
__device__ float g_pre[(size_t)2 * MROWS * GDIM];   // [dir][row][192]
__device__ float g_hbuf[(size_t)MROWS * 128];       // [row][2*H]

typedef unsigned long long u64;

__device__ __forceinline__ u64 fma2(u64 a, u64 b, u64 c) {
    u64 d;
    asm("fma.rn.f32x2 %0, %1, %2, %3;" : "=l"(d) : "l"(a), "l"(b), "l"(c));
    return d;
}
__device__ __forceinline__ float2 u2f(u64 v) {
    float2 r;
    asm("mov.b64 {%0,%1}, %2;" : "=f"(r.x), "=f"(r.y) : "l"(v));
    return r;
}
__device__ __forceinline__ float tanh_fast(float x) {
    float y;
    asm("tanh.approx.f32 %0, %1;" : "=f"(y) : "f"(x));
    return y;
}
__device__ __forceinline__ float sig_fast(float x) {
    return 0.5f * tanh_fast(0.5f * x) + 0.5f;
}
__device__ __forceinline__ float sig_acc(float x) {
    return __fdividef(1.f, 1.f + __expf(-x));
}

// ---------------- layer-0 projection (KD=64): 2 gate rows per thread ----------------
__global__ __launch_bounds__(192, 2)
void proj0_kernel(const float* __restrict__ xin,
                  const float* __restrict__ W,     // [384][64]
                  const float* __restrict__ bias)  // [384]
{
    const int tid  = threadIdx.x;
    const int row0 = blockIdx.x * 256;

    __shared__ __align__(16) float xs[2][32 * 64];

    const int j0 = 2 * tid;
    const int d  = (j0 >= GDIM) ? 1 : 0;
    const int g0 = j0 - d * GDIM;

    u64 w[2][32];
    const u64* wr = (const u64*)(W + (size_t)j0 * 64);
#pragma unroll
    for (int q = 0; q < 32; q++) { w[0][q] = wr[q]; w[1][q] = wr[32 + q]; }
    const float2 b2 = *(const float2*)(bias + j0);

    float* op = g_pre + ((size_t)d * MROWS + row0) * GDIM + g0;

    {   // chunk 0 (contiguous copy)
        const float4* s4 = (const float4*)(xin + (size_t)row0 * 64);
        for (int i = tid; i < 512; i += 192) ((float4*)xs[0])[i] = s4[i];
    }
    __syncthreads();

#pragma unroll 1
    for (int c = 0; c < 8; c++) {
        const int buf = c & 1;
        if (c < 7) {
            const float4* s4 = (const float4*)(xin + (size_t)(row0 + (c + 1) * 32) * 64);
            for (int i = tid; i < 512; i += 192) ((float4*)xs[buf ^ 1])[i] = s4[i];
        }
#pragma unroll 1
        for (int r = 0; r < 32; r++) {
            const ulonglong2* xp = (const ulonglong2*)(xs[buf] + r * 64);
            u64 a0 = 0, a1 = 0, a2 = 0, a3 = 0;
#pragma unroll
            for (int q = 0; q < 16; q++) {
                ulonglong2 v = xp[q];
                a0 = fma2(w[0][2 * q + 0], v.x, a0);
                a1 = fma2(w[0][2 * q + 1], v.y, a1);
                a2 = fma2(w[1][2 * q + 0], v.x, a2);
                a3 = fma2(w[1][2 * q + 1], v.y, a3);
            }
            float2 f0 = u2f(a0), f1 = u2f(a1), f2_ = u2f(a2), f3 = u2f(a3);
            float s0 = (f0.x + f0.y) + (f1.x + f1.y) + b2.x;
            float s1 = (f2_.x + f2_.y) + (f3.x + f3.y) + b2.y;
            *(float2*)(op + (size_t)(c * 32 + r) * GDIM) = make_float2(s0, s1);
        }
        __syncthreads();
    }
}

// ---------------- layer-1 projection (KD=128): split-K pairs, ONE dir per CTA ----------------
__global__ __launch_bounds__(192, 2)
void proj1_kernel(const float* __restrict__ W,     // [2][192][128]
                  const float* __restrict__ bias)  // [2][192]
{
    const float* in = (const float*)g_hbuf;
    const int tid  = threadIdx.x;
    const int row0 = blockIdx.x * 256;
    const int d    = blockIdx.y;

    __shared__ __align__(16) float xs[2][32 * 132];   // 132 = 64 + 4 pad + 64

    const int m  = tid >> 1;          // 0..95 -> rows 2m, 2m+1 of this dir
    const int kh = tid & 1;
    const int g0 = 2 * m;

    u64 w[2][32];
    const u64* wr = (const u64*)(W + ((size_t)d * GDIM + g0) * 128);
#pragma unroll
    for (int q = 0; q < 32; q++) {
        w[0][q] = wr[kh * 32 + q];
        w[1][q] = wr[64 + kh * 32 + q];
    }
    const float2 b2 = *(const float2*)(bias + d * GDIM + g0);

    float* op = g_pre + ((size_t)d * MROWS + row0) * GDIM + g0;

    auto load_chunk = [&](int c, int buf) {
        const float4* s4 = (const float4*)(in + (size_t)(row0 + c * 32) * 128);
        for (int i = tid; i < 1024; i += 192) {
            int r = i >> 5, jj = i & 31;
            int dstf = r * 132 + ((jj < 16) ? jj * 4 : 68 + (jj - 16) * 4);
            *(float4*)(xs[buf] + dstf) = s4[i];
        }
    };

    load_chunk(0, 0);
    __syncthreads();

#pragma unroll 1
    for (int c = 0; c < 8; c++) {
        const int buf = c & 1;
        if (c < 7) load_chunk(c + 1, buf ^ 1);
#pragma unroll 1
        for (int r = 0; r < 32; r++) {
            const ulonglong2* xp = (const ulonglong2*)(xs[buf] + r * 132 + kh * 68);
            u64 a0 = 0, a1 = 0, a2 = 0, a3 = 0;
#pragma unroll
            for (int q = 0; q < 16; q++) {
                ulonglong2 v = xp[q];
                a0 = fma2(w[0][2 * q + 0], v.x, a0);
                a1 = fma2(w[0][2 * q + 1], v.y, a1);
                a2 = fma2(w[1][2 * q + 0], v.x, a2);
                a3 = fma2(w[1][2 * q + 1], v.y, a3);
            }
            float2 f0 = u2f(a0), f1 = u2f(a1), f2_ = u2f(a2), f3 = u2f(a3);
            float s0 = (f0.x + f0.y) + (f1.x + f1.y);
            float s1 = (f2_.x + f2_.y) + (f3.x + f3.y);
            s0 += __shfl_xor_sync(0xffffffffu, s0, 1);
            s1 += __shfl_xor_sync(0xffffffffu, s1, 1);
            if (kh == 0)
                *(float2*)(op + (size_t)(c * 32 + r) * GDIM) =
                    make_float2(s0 + b2.x, s1 + b2.y);
        }
        __syncthreads();
    }
}

// ---------------- recurrence v4: gate-aligned threads, ONE barrier per step ----------------
// 64 threads/CTA; thread i owns ALL THREE gate rows (r,z,n) of hidden unit i
// (96 u64 weight regs). After the 3 dots it activates locally and writes
// h_new[i] into the double-buffered h_sh — no s_v stage, single barrier/step.
__global__ __launch_bounds__(64, 4)
void recur_kernel(const float* __restrict__ Whh,   // [2][192][64]
                  const float* __restrict__ bhh)   // [2][192]
{
    const int d  = blockIdx.y;
    const int n0 = blockIdx.x * RSPC;
    const int i  = threadIdx.x;          // hidden unit 0..63

    __shared__ float h_sh[2][RSPC][64];

    // weight rows i (r), 64+i (z), 128+i (n) for dir d
    u64 w[3][32];
#pragma unroll
    for (int g = 0; g < 3; g++) {
        const u64* wr = (const u64*)(Whh + ((size_t)d * GDIM + g * 64 + i) * HDIM);
#pragma unroll
        for (int q = 0; q < 32; q++) w[g][q] = wr[q];
    }
    const float b_r = bhh[d * GDIM + i];
    const float b_z = bhh[d * GDIM + 64 + i];
    const float b_n = bhh[d * GDIM + 128 + i];

#pragma unroll
    for (int s = 0; s < RSPC; s++) h_sh[0][s][i] = 0.f;
    __syncthreads();

    const int t0  = d ? (TT - 1) : 0;
    const int dt  = d ? -1 : 1;
    const long dtG = (long)dt * GDIM;
    const long dtH = (long)dt * 128;

    // per-seq pre pointers + output pointers (tail CTA clamps reads, gates stores)
    const float* pp[RSPC];
    float* hp[RSPC];
    bool vs[RSPC];
#pragma unroll
    for (int s = 0; s < RSPC; s++) {
        int n = n0 + s;
        vs[s] = (n < NSEQ);
        int nc = vs[s] ? n : (NSEQ - 1);
        pp[s] = g_pre + ((size_t)d * MROWS + (size_t)nc * TT + t0) * GDIM + i;
        hp[s] = g_hbuf + ((size_t)nc * TT + t0) * 128 + d * 64 + i;
    }

    float pr[RSPC], pz[RSPC], pnn[RSPC];
#pragma unroll
    for (int s = 0; s < RSPC; s++) {
        pr[s]  = __ldg(pp[s]);
        pz[s]  = __ldg(pp[s] + 64);
        pnn[s] = __ldg(pp[s] + 128);
        pp[s] += dtG;
    }

#pragma unroll 1
    for (int step = 0; step < TT; step++) {
        const int buf = step & 1;
        float qr[RSPC], qz[RSPC], qn[RSPC];
        if (step < TT - 1) {
#pragma unroll
            for (int s = 0; s < RSPC; s++) {
                qr[s] = __ldg(pp[s]);
                qz[s] = __ldg(pp[s] + 64);
                qn[s] = __ldg(pp[s] + 128);
                pp[s] += dtG;
            }
        }

#pragma unroll
        for (int s = 0; s < RSPC; s++) {
            const ulonglong2* h2 = (const ulonglong2*)h_sh[buf][s];
            float hold = h_sh[buf][s][i];
            u64 ar0 = 0, ar1 = 0, az0 = 0, az1 = 0, an0 = 0, an1 = 0;
#pragma unroll
            for (int q = 0; q < 16; q++) {
                ulonglong2 v = h2[q];
                ar0 = fma2(w[0][2 * q + 0], v.x, ar0);
                ar1 = fma2(w[0][2 * q + 1], v.y, ar1);
                az0 = fma2(w[1][2 * q + 0], v.x, az0);
                az1 = fma2(w[1][2 * q + 1], v.y, az1);
                an0 = fma2(w[2][2 * q + 0], v.x, an0);
                an1 = fma2(w[2][2 * q + 1], v.y, an1);
            }
            float2 fr0 = u2f(ar0), fr1 = u2f(ar1);
            float2 fz0 = u2f(az0), fz1 = u2f(az1);
            float2 fn0 = u2f(an0), fn1 = u2f(an1);
            float hr = (fr0.x + fr0.y) + (fr1.x + fr1.y) + b_r;
            float hz = (fz0.x + fz0.y) + (fz1.x + fz1.y) + b_z;
            float hn = (fn0.x + fn0.y) + (fn1.x + fn1.y) + b_n;

            float r    = sig_fast(pr[s] + hr);
            float z    = sig_fast(pz[s] + hz);
            float nn   = tanh_fast(pnn[s] + r * hn);
            float hnew = nn + z * (hold - nn);

            h_sh[buf ^ 1][s][i] = hnew;
            if (vs[s]) *hp[s] = hnew;
            hp[s] += dtH;
        }
        __syncthreads();

#pragma unroll
        for (int s = 0; s < RSPC; s++) { pr[s] = qr[s]; pz[s] = qz[s]; pnn[s] = qn[s]; }
    }
}

// ---------------- FC head: 2 outputs per warp (MLP=2) ----------------
__global__ void fc_kernel(const float* __restrict__ fcw,
                          const float* __restrict__ fcb,
                          float* __restrict__ out)
{
    int wid  = threadIdx.x >> 5;
    int lane = threadIdx.x & 31;
    size_t g0 = (size_t)blockIdx.x * 16 + wid * 2;

    float4 w4 = *(const float4*)(fcw + lane * 4);
    float4 v0 = *(const float4*)(g_hbuf + g0 * 128 + lane * 4);
    float4 v1 = *(const float4*)(g_hbuf + (g0 + 1) * 128 + lane * 4);
    float d0 = v0.x * w4.x + v0.y * w4.y + v0.z * w4.z + v0.w * w4.w;
    float d1 = v1.x * w4.x + v1.y * w4.y + v1.z * w4.z + v1.w * w4.w;
#pragma unroll
    for (int o = 16; o > 0; o >>= 1) {
        d0 += __shfl_down_sync(0xffffffffu, d0, o);
        d1 += __shfl_down_sync(0xffffffffu, d1, o);
    }
    if (lane == 0) {
        float bb = fcb[0];
#pragma unroll
        for (int k = 0; k < 2; k++) {
            size_t g = g0 + k;
            float dv = k ? d1 : d0;
            int nidx = (int)(g / TT), t = (int)(g % TT);
            int b = nidx / 88, f = nidx % 88;
            out[((size_t)b * TT + t) * 88 + f] = sig_acc(dv + bb);
        }
    }
}

// ---------------- launch ----------------
extern "C" void kernel_launch(void* const* d_in, const int* in_sizes, int n_in,
                              void* d_out, int out_size)
{
    const float* x    = (const float*)d_in[0];
    const float* Wih0 = (const float*)d_in[1];
    const float* Whh0 = (const float*)d_in[2];
    const float* bih0 = (const float*)d_in[3];
    const float* bhh0 = (const float*)d_in[4];
    const float* Wih1 = (const float*)d_in[5];
    const float* Whh1 = (const float*)d_in[6];
    const float* bih1 = (const float*)d_in[7];
    const float* bhh1 = (const float*)d_in[8];
    const float* fcw  = (const float*)d_in[9];
    const float* fcb  = (const float*)d_in[10];
    float* out = (float*)d_out;

    dim3 rg(NCTA_R, 2);
    dim3 p1g(MROWS / 256, 2);

    proj0_kernel<<<MROWS / 256, 192>>>(x, Wih0, bih0);      // L0 input proj
    recur_kernel<<<rg, 64>>>(Whh0, bhh0);                   // L0 GRU
    proj1_kernel<<<p1g, 192>>>(Wih1, bih1);                 // L1 input proj (reads g_hbuf)
    recur_kernel<<<rg, 64>>>(Whh1, bhh1);                   // L1 GRU
    fc_kernel<<<MROWS / 16, 256>>>(fcw, fcb, out);          // FC + sigmoid
}

// round 17
// speedup vs baseline: 1.4113x; 1.1465x over previous
#include <cuda_runtime.h>

// ---------------- problem constants ----------------
#define NSEQ  704          // B*F
#define TT    512
#define HDIM  64
#define GDIM  192          // 3*H
#define MROWS (NSEQ*TT)    // 360448
#define RSPC  3            // sequences per recur CTA (per dir)
#define NCTA_R ((NSEQ + RSPC - 1) / RSPC)   // 235

// ---------------- scratch (device globals; no allocation) ----------------
__device__ float g_pre[(size_t)2 * MROWS * GDIM];   // [dir][row][192]
__device__ float g_hbuf[(size_t)MROWS * 128];       // [row][2*H]

typedef unsigned long long u64;
typedef unsigned int u32;

__device__ __forceinline__ u64 fma2(u64 a, u64 b, u64 c) {
    u64 d;
    asm("fma.rn.f32x2 %0, %1, %2, %3;" : "=l"(d) : "l"(a), "l"(b), "l"(c));
    return d;
}
__device__ __forceinline__ float2 u2f(u64 v) {
    float2 r;
    asm("mov.b64 {%0,%1}, %2;" : "=f"(r.x), "=f"(r.y) : "l"(v));
    return r;
}
__device__ __forceinline__ float tanh_fast(float x) {
    float y;
    asm("tanh.approx.f32 %0, %1;" : "=f"(y) : "f"(x));
    return y;
}
__device__ __forceinline__ float sig_fast(float x) {
    return 0.5f * tanh_fast(0.5f * x) + 0.5f;
}
__device__ __forceinline__ float sig_acc(float x) {
    return __fdividef(1.f, 1.f + __expf(-x));
}

// ---- tf32 helpers ----
__device__ __forceinline__ void tf32_split(float v, u32& hi, u32& lo) {
    u32 h;
    asm("cvt.rna.tf32.f32 %0, %1;" : "=r"(h) : "f"(v));
    float r = v - __uint_as_float(h);
    u32 l;
    asm("cvt.rna.tf32.f32 %0, %1;" : "=r"(l) : "f"(r));
    hi = h; lo = l;
}
__device__ __forceinline__ void mma_tf32(float4& c,
                                         u32 a0, u32 a1, u32 a2, u32 a3,
                                         u32 b0, u32 b1) {
    asm("mma.sync.aligned.m16n8k8.row.col.f32.tf32.tf32.f32 "
        "{%0,%1,%2,%3}, {%4,%5,%6,%7}, {%8,%9}, {%0,%1,%2,%3};"
        : "+f"(c.x), "+f"(c.y), "+f"(c.z), "+f"(c.w)
        : "r"(a0), "r"(a1), "r"(a2), "r"(a3), "r"(b0), "r"(b1));
}

// ---------------- projection via 3xTF32 tensor-core GEMM ----------------
// pre[M,384] = in[M,KD] @ W[384,KD]^T + bias.  CTA: 256 thr / 8 warps,
// tile M=128 x N=64 (blockIdx.y picks 64-col slice; slices never straddle the
// dir boundary at 192). K in chunks of 16. x/W split into tf32 hi+lo; C
// accumulates hi*hi + hi*lo + lo*hi in fp32 (error ~2^-22).
// smem rows padded to 20 words -> conflict-free scalar LDS for fragments.
template<int KD>
__global__ __launch_bounds__(256, 2)
void proj_mma_kernel(const float* __restrict__ xin,
                     const float* __restrict__ W,     // [384][KD]
                     const float* __restrict__ bias)  // [384]
{
    const float* in = (KD == 64) ? xin : (const float*)g_hbuf;

    __shared__ u32 xs_hi[128 * 20], xs_lo[128 * 20];
    __shared__ u32 ws_hi[64 * 20],  ws_lo[64 * 20];

    const int tid   = threadIdx.x;
    const int lane  = tid & 31;
    const int wid   = tid >> 5;
    const int gid   = lane >> 2;    // 0..7
    const int tid4  = lane & 3;     // 0..3
    const int wm    = wid & 3;      // 0..3  (M 32-slice)
    const int wn    = wid >> 2;     // 0..1  (N 32-slice)
    const int rbase = blockIdx.x * 128;
    const int n0    = blockIdx.y * 64;

    float4 C[2][4];
#pragma unroll
    for (int mt = 0; mt < 2; mt++)
#pragma unroll
        for (int nt = 0; nt < 4; nt++) C[mt][nt] = make_float4(0.f, 0.f, 0.f, 0.f);

#pragma unroll 1
    for (int kc = 0; kc < KD / 16; kc++) {
        const int K0 = kc * 16;
        // ---- load X chunk: 128 rows x 16 k (512 float4) ----
#pragma unroll
        for (int it = 0; it < 2; it++) {
            int i = tid + it * 256;
            int m = i >> 2, j = i & 3;
            float4 v = *(const float4*)(in + (size_t)(rbase + m) * KD + K0 + 4 * j);
            u32 h0, l0, h1, l1, h2, l2, h3, l3;
            tf32_split(v.x, h0, l0); tf32_split(v.y, h1, l1);
            tf32_split(v.z, h2, l2); tf32_split(v.w, h3, l3);
            int o = m * 20 + 4 * j;
            *(uint4*)&xs_hi[o] = make_uint4(h0, h1, h2, h3);
            *(uint4*)&xs_lo[o] = make_uint4(l0, l1, l2, l3);
        }
        // ---- load W chunk: 64 rows x 16 k (256 float4) ----
        {
            int n = tid >> 2, j = tid & 3;
            float4 v = *(const float4*)(W + (size_t)(n0 + n) * KD + K0 + 4 * j);
            u32 h0, l0, h1, l1, h2, l2, h3, l3;
            tf32_split(v.x, h0, l0); tf32_split(v.y, h1, l1);
            tf32_split(v.z, h2, l2); tf32_split(v.w, h3, l3);
            int o = n * 20 + 4 * j;
            *(uint4*)&ws_hi[o] = make_uint4(h0, h1, h2, h3);
            *(uint4*)&ws_lo[o] = make_uint4(l0, l1, l2, l3);
        }
        __syncthreads();

        // ---- compute: 2 k-steps of m16n8k8 ----
#pragma unroll
        for (int ks = 0; ks < 2; ks++) {
            const int k0 = ks * 8;
            u32 bh0[4], bh1[4], bl0[4], bl1[4];
#pragma unroll
            for (int nt = 0; nt < 4; nt++) {
                int bi = (wn * 32 + nt * 8 + gid) * 20 + tid4 + k0;
                bh0[nt] = ws_hi[bi]; bh1[nt] = ws_hi[bi + 4];
                bl0[nt] = ws_lo[bi]; bl1[nt] = ws_lo[bi + 4];
            }
#pragma unroll
            for (int mt = 0; mt < 2; mt++) {
                int ia = (wm * 32 + mt * 16 + gid) * 20 + tid4 + k0;
                int ib = ia + 8 * 20;
                u32 ah0 = xs_hi[ia], ah1 = xs_hi[ib], ah2 = xs_hi[ia + 4], ah3 = xs_hi[ib + 4];
                u32 al0 = xs_lo[ia], al1 = xs_lo[ib], al2 = xs_lo[ia + 4], al3 = xs_lo[ib + 4];
#pragma unroll
                for (int nt = 0; nt < 4; nt++) {
                    mma_tf32(C[mt][nt], ah0, ah1, ah2, ah3, bh0[nt], bh1[nt]);
                    mma_tf32(C[mt][nt], ah0, ah1, ah2, ah3, bl0[nt], bl1[nt]);
                    mma_tf32(C[mt][nt], al0, al1, al2, al3, bh0[nt], bh1[nt]);
                }
            }
        }
        __syncthreads();
    }

    // ---- epilogue: bias + store to g_pre ----
    const int d = (n0 >= GDIM) ? 1 : 0;
#pragma unroll
    for (int nt = 0; nt < 4; nt++) {
        int j0 = n0 + wn * 32 + nt * 8 + 2 * tid4;
        float2 bb = *(const float2*)(bias + j0);
        int g0 = j0 - d * GDIM;
#pragma unroll
        for (int mt = 0; mt < 2; mt++) {
            int r0 = rbase + wm * 32 + mt * 16 + gid;
            float4 c = C[mt][nt];
            *(float2*)(g_pre + ((size_t)d * MROWS + r0) * GDIM + g0) =
                make_float2(c.x + bb.x, c.y + bb.y);
            *(float2*)(g_pre + ((size_t)d * MROWS + r0 + 8) * GDIM + g0) =
                make_float2(c.z + bb.x, c.w + bb.y);
        }
    }
}

// ---------------- recurrence v4: gate-aligned threads, ONE barrier per step ----------------
__global__ __launch_bounds__(64, 4)
void recur_kernel(const float* __restrict__ Whh,   // [2][192][64]
                  const float* __restrict__ bhh)   // [2][192]
{
    const int d  = blockIdx.y;
    const int n0 = blockIdx.x * RSPC;
    const int i  = threadIdx.x;          // hidden unit 0..63

    __shared__ float h_sh[2][RSPC][64];

    u64 w[3][32];
#pragma unroll
    for (int g = 0; g < 3; g++) {
        const u64* wr = (const u64*)(Whh + ((size_t)d * GDIM + g * 64 + i) * HDIM);
#pragma unroll
        for (int q = 0; q < 32; q++) w[g][q] = wr[q];
    }
    const float b_r = bhh[d * GDIM + i];
    const float b_z = bhh[d * GDIM + 64 + i];
    const float b_n = bhh[d * GDIM + 128 + i];

#pragma unroll
    for (int s = 0; s < RSPC; s++) h_sh[0][s][i] = 0.f;
    __syncthreads();

    const int t0  = d ? (TT - 1) : 0;
    const int dt  = d ? -1 : 1;
    const long dtG = (long)dt * GDIM;
    const long dtH = (long)dt * 128;

    const float* pp[RSPC];
    float* hp[RSPC];
    bool vs[RSPC];
#pragma unroll
    for (int s = 0; s < RSPC; s++) {
        int n = n0 + s;
        vs[s] = (n < NSEQ);
        int nc = vs[s] ? n : (NSEQ - 1);
        pp[s] = g_pre + ((size_t)d * MROWS + (size_t)nc * TT + t0) * GDIM + i;
        hp[s] = g_hbuf + ((size_t)nc * TT + t0) * 128 + d * 64 + i;
    }

    float pr[RSPC], pz[RSPC], pnn[RSPC];
#pragma unroll
    for (int s = 0; s < RSPC; s++) {
        pr[s]  = __ldg(pp[s]);
        pz[s]  = __ldg(pp[s] + 64);
        pnn[s] = __ldg(pp[s] + 128);
        pp[s] += dtG;
    }

#pragma unroll 1
    for (int step = 0; step < TT; step++) {
        const int buf = step & 1;
        float qr[RSPC], qz[RSPC], qn[RSPC];
        if (step < TT - 1) {
#pragma unroll
            for (int s = 0; s < RSPC; s++) {
                qr[s] = __ldg(pp[s]);
                qz[s] = __ldg(pp[s] + 64);
                qn[s] = __ldg(pp[s] + 128);
                pp[s] += dtG;
            }
        }

#pragma unroll
        for (int s = 0; s < RSPC; s++) {
            const ulonglong2* h2 = (const ulonglong2*)h_sh[buf][s];
            float hold = h_sh[buf][s][i];
            u64 ar0 = 0, ar1 = 0, az0 = 0, az1 = 0, an0 = 0, an1 = 0;
#pragma unroll
            for (int q = 0; q < 16; q++) {
                ulonglong2 v = h2[q];
                ar0 = fma2(w[0][2 * q + 0], v.x, ar0);
                ar1 = fma2(w[0][2 * q + 1], v.y, ar1);
                az0 = fma2(w[1][2 * q + 0], v.x, az0);
                az1 = fma2(w[1][2 * q + 1], v.y, az1);
                an0 = fma2(w[2][2 * q + 0], v.x, an0);
                an1 = fma2(w[2][2 * q + 1], v.y, an1);
            }
            float2 fr0 = u2f(ar0), fr1 = u2f(ar1);
            float2 fz0 = u2f(az0), fz1 = u2f(az1);
            float2 fn0 = u2f(an0), fn1 = u2f(an1);
            float hr = (fr0.x + fr0.y) + (fr1.x + fr1.y) + b_r;
            float hz = (fz0.x + fz0.y) + (fz1.x + fz1.y) + b_z;
            float hn = (fn0.x + fn0.y) + (fn1.x + fn1.y) + b_n;

            float r    = sig_fast(pr[s] + hr);
            float z    = sig_fast(pz[s] + hz);
            float nn   = tanh_fast(pnn[s] + r * hn);
            float hnew = nn + z * (hold - nn);

            h_sh[buf ^ 1][s][i] = hnew;
            if (vs[s]) *hp[s] = hnew;
            hp[s] += dtH;
        }
        __syncthreads();

#pragma unroll
        for (int s = 0; s < RSPC; s++) { pr[s] = qr[s]; pz[s] = qz[s]; pnn[s] = qn[s]; }
    }
}

// ---------------- FC head: 2 outputs per warp (MLP=2) ----------------
__global__ void fc_kernel(const float* __restrict__ fcw,
                          const float* __restrict__ fcb,
                          float* __restrict__ out)
{
    int wid  = threadIdx.x >> 5;
    int lane = threadIdx.x & 31;
    size_t g0 = (size_t)blockIdx.x * 16 + wid * 2;

    float4 w4 = *(const float4*)(fcw + lane * 4);
    float4 v0 = *(const float4*)(g_hbuf + g0 * 128 + lane * 4);
    float4 v1 = *(const float4*)(g_hbuf + (g0 + 1) * 128 + lane * 4);
    float d0 = v0.x * w4.x + v0.y * w4.y + v0.z * w4.z + v0.w * w4.w;
    float d1 = v1.x * w4.x + v1.y * w4.y + v1.z * w4.z + v1.w * w4.w;
#pragma unroll
    for (int o = 16; o > 0; o >>= 1) {
        d0 += __shfl_down_sync(0xffffffffu, d0, o);
        d1 += __shfl_down_sync(0xffffffffu, d1, o);
    }
    if (lane == 0) {
        float bb = fcb[0];
#pragma unroll
        for (int k = 0; k < 2; k++) {
            size_t g = g0 + k;
            float dv = k ? d1 : d0;
            int nidx = (int)(g / TT), t = (int)(g % TT);
            int b = nidx / 88, f = nidx % 88;
            out[((size_t)b * TT + t) * 88 + f] = sig_acc(dv + bb);
        }
    }
}

// ---------------- launch ----------------
extern "C" void kernel_launch(void* const* d_in, const int* in_sizes, int n_in,
                              void* d_out, int out_size)
{
    const float* x    = (const float*)d_in[0];
    const float* Wih0 = (const float*)d_in[1];
    const float* Whh0 = (const float*)d_in[2];
    const float* bih0 = (const float*)d_in[3];
    const float* bhh0 = (const float*)d_in[4];
    const float* Wih1 = (const float*)d_in[5];
    const float* Whh1 = (const float*)d_in[6];
    const float* bih1 = (const float*)d_in[7];
    const float* bhh1 = (const float*)d_in[8];
    const float* fcw  = (const float*)d_in[9];
    const float* fcb  = (const float*)d_in[10];
    float* out = (float*)d_out;

    dim3 rg(NCTA_R, 2);
    dim3 pg(MROWS / 128, 6);

    proj_mma_kernel<64><<<pg, 256>>>(x, Wih0, bih0);    // L0 input proj (tf32 MMA)
    recur_kernel<<<rg, 64>>>(Whh0, bhh0);               // L0 GRU
    proj_mma_kernel<128><<<pg, 256>>>(x, Wih1, bih1);   // L1 input proj (tf32 MMA)
    recur_kernel<<<rg, 64>>>(Whh1, bhh1);               // L1 GRU
    fc_kernel<<<MROWS / 16, 256>>>(fcw, fcb, out);      // FC + sigmoid
}